// round 8
// baseline (speedup 1.0000x reference)
#include <cuda_runtime.h>
#include <cuda_bf16.h>
#include <math.h>

// Problem constants
#define BB   8
#define TT   4096
#define DD   256
#define MM   8
#define CHUNK 32
#define SUB  8                  // subchunk length
#define NSUB (CHUNK / SUB)      // 4 subchunks per chunk
#define NC   (TT / CHUNK)       // 128 chunks along T
#define D4   (DD / 4)           // 64 float4 groups per row
#define RPB  (MM * D4)          // 512 float4 "r" slots per tile

// Scratch (static device allocations — no runtime alloc)
__device__ float g_Ls[(size_t)BB * NC * NSUB * MM * DD];  // subchunk local finals, 33.5 MB
__device__ float g_As[BB * NC * NSUB * MM];               // subchunk decay products
__device__ float g_S [(size_t)BB * NC * MM * DD];         // chunk initial states, 8 MB

// ---------------------------------------------------------------------------
// Kernel 1: per-subchunk local recurrence (s starts at 0) -> g_Ls, g_As.
// Block = (b, c). 256 threads: tid = g*64 + d4; group g owns subchunk g,
// all 8 m, x read straight to registers (1x coalesced LDG, no smem x tile).
// ---------------------------------------------------------------------------
__global__ __launch_bounds__(256) void k_locals(
    const float* __restrict__ x, const float* __restrict__ delta,
    const float* __restrict__ tau)
{
    int blk = blockIdx.x;
    int b = blk >> 7;          // / NC
    int c = blk & (NC - 1);
    int t0 = c * CHUNK;
    int tid = threadIdx.x;
    int d4 = tid & 63;
    int g  = tid >> 6;         // subchunk 0..3

    __shared__ float2 s_al[CHUNK * MM];   // (a, 1-a) per (t, m)

    // warp 0: alphas for all 32 t, then subchunk products (lane = gg*8 + mm)
    if (tid < 32) {
        int t = t0 + tid;
        float dt = 0.0f;
        if (t > 0)
            dt = fmaxf(delta[b * TT + t] - delta[b * TT + t - 1], 0.0f);
#pragma unroll
        for (int m = 0; m < MM; m++) {
            float a = expf(-dt / tau[m]);
            s_al[tid * MM + m] = make_float2(a, 1.0f - a);
        }
        __syncwarp();
        int gg = tid >> 3, mm = tid & 7;
        float p = 1.0f;
#pragma unroll
        for (int t2 = 0; t2 < SUB; t2++) p *= s_al[(gg * SUB + t2) * MM + mm].x;
        g_As[((b * NC + c) * NSUB + gg) * MM + mm] = p;
    }

    // prefetch the 8 x rows of this thread's subchunk (independent LDG.128)
    const float4* xp = (const float4*)x + ((size_t)b * TT + t0 + g * SUB) * D4 + d4;
    float4 xv[SUB];
#pragma unroll
    for (int t = 0; t < SUB; t++) xv[t] = __ldg(xp + t * D4);

    __syncthreads();   // alphas ready

    float4 s[MM];
#pragma unroll
    for (int m = 0; m < MM; m++) s[m] = make_float4(0.f, 0.f, 0.f, 0.f);

#pragma unroll
    for (int t = 0; t < SUB; t++) {
#pragma unroll
        for (int m = 0; m < MM; m++) {
            float2 al = s_al[(g * SUB + t) * MM + m];
            s[m].x = fmaf(al.x, s[m].x, al.y * xv[t].x);
            s[m].y = fmaf(al.x, s[m].y, al.y * xv[t].y);
            s[m].z = fmaf(al.x, s[m].z, al.y * xv[t].z);
            s[m].w = fmaf(al.x, s[m].w, al.y * xv[t].w);
        }
    }

    float4* Lp = (float4*)g_Ls + ((size_t)(b * NC + c) * NSUB + g) * RPB + d4;
#pragma unroll
    for (int m = 0; m < MM; m++) Lp[m * D4] = s[m];
}

// ---------------------------------------------------------------------------
// Kernel 2: sequential scan over 512 subchunks per (b, m, d4) chain;
// writes chunk-initial states (exclusive, at chunk granularity).
// ---------------------------------------------------------------------------
__global__ __launch_bounds__(64) void k_scan()
{
    int idx = blockIdx.x * 64 + threadIdx.x;    // 0 .. B*M*D4-1 = 4095
    int b = idx >> 9;          // / RPB
    int r = idx & (RPB - 1);
    int m = r >> 6;            // / D4

    const float4* Lp = (const float4*)g_Ls;
    float4* Sp = (float4*)g_S;

    float4 s = make_float4(0.f, 0.f, 0.f, 0.f);
#pragma unroll 2
    for (int c = 0; c < NC; c++) {
        Sp[(size_t)(b * NC + c) * RPB + r] = s;
#pragma unroll
        for (int gg = 0; gg < NSUB; gg++) {
            size_t soff = ((size_t)(b * NC + c) * NSUB + gg) * RPB + r;
            float4 L = __ldg(Lp + soff);
            float  A = __ldg(&g_As[((b * NC + c) * NSUB + gg) * MM + m]);
            s.x = fmaf(A, s.x, L.x);
            s.y = fmaf(A, s.y, L.y);
            s.z = fmaf(A, s.z, L.z);
            s.w = fmaf(A, s.w, L.w);
        }
    }
}

// ---------------------------------------------------------------------------
// Kernel 3: replay. Block = (b, c). Group g: fold subchunks 0..g-1 onto the
// chunk-initial state, then run subchunk g's 8 steps with x in registers.
// Streaming stores for the 256 MB output.
// ---------------------------------------------------------------------------
__global__ __launch_bounds__(256) void k_final(
    const float* __restrict__ x, const float* __restrict__ delta,
    const float* __restrict__ tau, float* __restrict__ out)
{
    int blk = blockIdx.x;
    int b = blk >> 7;
    int c = blk & (NC - 1);
    int t0 = c * CHUNK;
    int tid = threadIdx.x;
    int d4 = tid & 63;
    int g  = tid >> 6;

    __shared__ float2 s_al[CHUNK * MM];
    __shared__ float  s_Ag[NSUB * MM];

    if (tid < 32) {
        int t = t0 + tid;
        float dt = 0.0f;
        if (t > 0)
            dt = fmaxf(delta[b * TT + t] - delta[b * TT + t - 1], 0.0f);
#pragma unroll
        for (int m = 0; m < MM; m++) {
            float a = expf(-dt / tau[m]);
            s_al[tid * MM + m] = make_float2(a, 1.0f - a);
        }
        __syncwarp();
        int gg = tid >> 3, mm = tid & 7;
        float p = 1.0f;
#pragma unroll
        for (int t2 = 0; t2 < SUB; t2++) p *= s_al[(gg * SUB + t2) * MM + mm].x;
        s_Ag[gg * MM + mm] = p;
    }

    // prefetch x rows of this subchunk (independent LDG.128)
    const float4* xp = (const float4*)x + ((size_t)b * TT + t0 + g * SUB) * D4 + d4;
    float4 xv[SUB];
#pragma unroll
    for (int t = 0; t < SUB; t++) xv[t] = __ldg(xp + t * D4);

    // chunk-initial state (all groups read the same tile -> L1/L2 hits)
    const float4* Sp = (const float4*)g_S + (size_t)(b * NC + c) * RPB + d4;
    float4 s[MM];
#pragma unroll
    for (int m = 0; m < MM; m++) s[m] = Sp[m * D4];

    __syncthreads();   // alphas + s_Ag ready

    // fold preceding subchunks: s = A[gg]*s + L[gg], gg = 0..g-1
#pragma unroll
    for (int gg = 0; gg < NSUB - 1; gg++) {
        if (gg < g) {
            const float4* Lp = (const float4*)g_Ls +
                ((size_t)(b * NC + c) * NSUB + gg) * RPB + d4;
#pragma unroll
            for (int m = 0; m < MM; m++) {
                float  A = s_Ag[gg * MM + m];
                float4 L = __ldg(Lp + m * D4);
                s[m].x = fmaf(A, s[m].x, L.x);
                s[m].y = fmaf(A, s[m].y, L.y);
                s[m].z = fmaf(A, s[m].z, L.z);
                s[m].w = fmaf(A, s[m].w, L.w);
            }
        }
    }

    // replay 8 steps, write out[((b*T+t)*M + m)*D + d]
    float4* op = (float4*)out + ((size_t)(b * TT + t0 + g * SUB)) * RPB + d4;
#pragma unroll
    for (int t = 0; t < SUB; t++) {
#pragma unroll
        for (int m = 0; m < MM; m++) {
            float2 al = s_al[(g * SUB + t) * MM + m];
            s[m].x = fmaf(al.x, s[m].x, al.y * xv[t].x);
            s[m].y = fmaf(al.x, s[m].y, al.y * xv[t].y);
            s[m].z = fmaf(al.x, s[m].z, al.y * xv[t].z);
            s[m].w = fmaf(al.x, s[m].w, al.y * xv[t].w);
            __stcs(op + (size_t)t * RPB + m * D4, s[m]);
        }
    }
}

extern "C" void kernel_launch(void* const* d_in, const int* in_sizes, int n_in,
                              void* d_out, int out_size)
{
    const float* x     = (const float*)d_in[0];
    const float* delta = (const float*)d_in[1];
    const float* tau   = (const float*)d_in[2];
    float* out = (float*)d_out;

    k_locals<<<BB * NC, 256>>>(x, delta, tau);
    k_scan<<<64, 64>>>();
    k_final<<<BB * NC, 256>>>(x, delta, tau, out);
}

// round 12
// speedup vs baseline: 1.0036x; 1.0036x over previous
#include <cuda_runtime.h>
#include <cuda_bf16.h>
#include <math.h>

// Problem constants
#define BB   8
#define TT   4096
#define DD   256
#define MM   8
#define CHUNK 32
#define SUB  8                  // subchunk length
#define NSUB (CHUNK / SUB)      // 4 subchunks per chunk
#define NC   (TT / CHUNK)       // 128 chunks along T
#define D4   (DD / 4)           // 64 float4 groups per row
#define RPB  (MM * D4)          // 512 float4 "r" slots per tile

// Scratch (static device allocations — no runtime alloc)
__device__ float g_Ls[(size_t)BB * NC * NSUB * MM * DD];  // subchunk local finals, 33.5 MB
__device__ float g_As[BB * NC * NSUB * MM];               // subchunk decay products
__device__ float g_S [(size_t)BB * NC * MM * DD];         // chunk initial states, 8 MB

// ---------------------------------------------------------------------------
// Kernel 1: per-subchunk local recurrence (s starts at 0) -> g_Ls, g_As.
// Block = (b, c). 256 threads: tid = g*64 + d4; group g owns subchunk g,
// all 8 m, x read straight to registers (1x coalesced LDG, no smem tile).
// [R8 verbatim — measured 14.9 us]
// ---------------------------------------------------------------------------
__global__ __launch_bounds__(256) void k_locals(
    const float* __restrict__ x, const float* __restrict__ delta,
    const float* __restrict__ tau)
{
    int blk = blockIdx.x;
    int b = blk >> 7;          // / NC
    int c = blk & (NC - 1);
    int t0 = c * CHUNK;
    int tid = threadIdx.x;
    int d4 = tid & 63;
    int g  = tid >> 6;         // subchunk 0..3

    __shared__ float2 s_al[CHUNK * MM];   // (a, 1-a) per (t, m)

    // warp 0: alphas for all 32 t, then subchunk products (lane = gg*8 + mm)
    if (tid < 32) {
        int t = t0 + tid;
        float dt = 0.0f;
        if (t > 0)
            dt = fmaxf(delta[b * TT + t] - delta[b * TT + t - 1], 0.0f);
#pragma unroll
        for (int m = 0; m < MM; m++) {
            float a = expf(-dt / tau[m]);
            s_al[tid * MM + m] = make_float2(a, 1.0f - a);
        }
        __syncwarp();
        int gg = tid >> 3, mm = tid & 7;
        float p = 1.0f;
#pragma unroll
        for (int t2 = 0; t2 < SUB; t2++) p *= s_al[(gg * SUB + t2) * MM + mm].x;
        g_As[((b * NC + c) * NSUB + gg) * MM + mm] = p;
    }

    // prefetch the 8 x rows of this thread's subchunk (independent LDG.128)
    const float4* xp = (const float4*)x + ((size_t)b * TT + t0 + g * SUB) * D4 + d4;
    float4 xv[SUB];
#pragma unroll
    for (int t = 0; t < SUB; t++) xv[t] = __ldg(xp + t * D4);

    __syncthreads();   // alphas ready

    float4 s[MM];
#pragma unroll
    for (int m = 0; m < MM; m++) s[m] = make_float4(0.f, 0.f, 0.f, 0.f);

#pragma unroll
    for (int t = 0; t < SUB; t++) {
#pragma unroll
        for (int m = 0; m < MM; m++) {
            float2 al = s_al[(g * SUB + t) * MM + m];
            s[m].x = fmaf(al.x, s[m].x, al.y * xv[t].x);
            s[m].y = fmaf(al.x, s[m].y, al.y * xv[t].y);
            s[m].z = fmaf(al.x, s[m].z, al.y * xv[t].z);
            s[m].w = fmaf(al.x, s[m].w, al.y * xv[t].w);
        }
    }

    float4* Lp = (float4*)g_Ls + ((size_t)(b * NC + c) * NSUB + g) * RPB + d4;
#pragma unroll
    for (int m = 0; m < MM; m++) Lp[m * D4] = s[m];
}

// ---------------------------------------------------------------------------
// Kernel 2: sequential scan over 512 subchunks per (b, m, d4) chain;
// writes chunk-initial states (exclusive, at chunk granularity).
// [R8 verbatim]
// ---------------------------------------------------------------------------
__global__ __launch_bounds__(64) void k_scan()
{
    int idx = blockIdx.x * 64 + threadIdx.x;    // 0 .. B*M*D4-1 = 4095
    int b = idx >> 9;          // / RPB
    int r = idx & (RPB - 1);
    int m = r >> 6;            // / D4

    const float4* Lp = (const float4*)g_Ls;
    float4* Sp = (float4*)g_S;

    float4 s = make_float4(0.f, 0.f, 0.f, 0.f);
#pragma unroll 2
    for (int c = 0; c < NC; c++) {
        Sp[(size_t)(b * NC + c) * RPB + r] = s;
#pragma unroll
        for (int gg = 0; gg < NSUB; gg++) {
            size_t soff = ((size_t)(b * NC + c) * NSUB + gg) * RPB + r;
            float4 L = __ldg(Lp + soff);
            float  A = __ldg(&g_As[((b * NC + c) * NSUB + gg) * MM + m]);
            s.x = fmaf(A, s.x, L.x);
            s.y = fmaf(A, s.y, L.y);
            s.z = fmaf(A, s.z, L.z);
            s.w = fmaf(A, s.w, L.w);
        }
    }
}

// ---------------------------------------------------------------------------
// Kernel 3: replay each chunk from its initial state, write all outputs.
// Block = (b, c). 512 threads: tid = m*64 + d4, ONE float4 state per thread.
// ~32 regs -> 4 blocks/SM (2048 thr, 100% occ) = max independent store streams.
// x staged once in 32 KB smem (8-way broadcast LDS); __stcs streaming stores.
// ---------------------------------------------------------------------------
__global__ __launch_bounds__(512) void k_final(
    const float* __restrict__ x, const float* __restrict__ delta,
    const float* __restrict__ tau, float* __restrict__ out)
{
    int blk = blockIdx.x;
    int b = blk >> 7;
    int c = blk & (NC - 1);
    int t0 = c * CHUNK;
    int tid = threadIdx.x;     // = m*64 + d4 = r
    int d4 = tid & 63;
    int m  = tid >> 6;

    __shared__ float2 s_al[CHUNK * MM];
    __shared__ float4 s_x[CHUNK * D4];      // 32 KB x tile

    if (tid < 32) {
        int t = t0 + tid;
        float dt = 0.0f;
        if (t > 0)
            dt = fmaxf(delta[b * TT + t] - delta[b * TT + t - 1], 0.0f);
#pragma unroll
        for (int mm = 0; mm < MM; mm++) {
            float a = expf(-dt / tau[mm]);
            s_al[tid * MM + mm] = make_float2(a, 1.0f - a);
        }
    }

    // cooperative coalesced x tile fill (4 independent LDG.128 per thread)
    {
        const float4* xp = (const float4*)x + ((size_t)b * TT + t0) * D4;
#pragma unroll
        for (int i = 0; i < (CHUNK * D4) / 512; i++)
            s_x[i * 512 + tid] = __ldg(xp + i * 512 + tid);
    }

    // chunk-initial state: r == tid, coalesced LDG.128
    float4 s = ((const float4*)g_S)[(size_t)(b * NC + c) * RPB + tid];

    __syncthreads();

    float4* op = (float4*)out + ((size_t)(b * TT + t0)) * RPB + tid;

#pragma unroll 8
    for (int t = 0; t < CHUNK; t++) {
        float4 xv = s_x[t * D4 + d4];          // 8-way broadcast across m
        float2 al = s_al[t * MM + m];
        s.x = fmaf(al.x, s.x, al.y * xv.x);
        s.y = fmaf(al.x, s.y, al.y * xv.y);
        s.z = fmaf(al.x, s.z, al.y * xv.z);
        s.w = fmaf(al.x, s.w, al.y * xv.w);
        __stcs(op + (size_t)t * RPB, s);       // contiguous 8 KB row per t
    }
}

extern "C" void kernel_launch(void* const* d_in, const int* in_sizes, int n_in,
                              void* d_out, int out_size)
{
    const float* x     = (const float*)d_in[0];
    const float* delta = (const float*)d_in[1];
    const float* tau   = (const float*)d_in[2];
    float* out = (float*)d_out;

    k_locals<<<BB * NC, 256>>>(x, delta, tau);
    k_scan<<<64, 64>>>();
    k_final<<<BB * NC, 512>>>(x, delta, tau, out);
}

// round 16
// speedup vs baseline: 1.8134x; 1.8069x over previous
#include <cuda_runtime.h>
#include <cuda_bf16.h>
#include <math.h>

// Problem constants
#define BB   8
#define TT   4096
#define DD   256
#define MM   8
#define CHUNK 32
#define NC   (TT / CHUNK)      // 128 chunks along T
#define D4   (DD / 4)          // 64 float4 groups per row
#define RPB  (MM * D4)         // 512 float4 "r" slots per (b,c)

// Scratch (static device allocations — no runtime alloc)
__device__ float g_L[(size_t)BB * NC * MM * DD];   // chunk-local final states, 8 MB
__device__ float g_S[(size_t)BB * NC * MM * DD];   // chunk initial states,     8 MB
__device__ float g_A[BB * NC * MM];                // chunk decay products

// ---------------------------------------------------------------------------
// Kernel 1: per-chunk local recurrence (s starts at 0), store L and A.
// [R4 verbatim — measured 17.6 us]
// Block = (b, c). 256 threads: tid = g*64 + d4, thread owns m = {2g, 2g+1}.
// x chunk staged through smem once.
// ---------------------------------------------------------------------------
__global__ __launch_bounds__(256) void k_locals(
    const float* __restrict__ x, const float* __restrict__ delta,
    const float* __restrict__ tau)
{
    int blk = blockIdx.x;
    int b = blk >> 7;          // / NC
    int c = blk & (NC - 1);
    int t0 = c * CHUNK;
    int tid = threadIdx.x;
    int d4 = tid & 63;
    int g  = tid >> 6;         // 0..3
    int m0 = g * 2;
    int m1 = m0 + 1;

    __shared__ float2 s_al[CHUNK * MM];     // (a, 1-a)
    __shared__ float4 s_x[CHUNK * D4];      // 32 KB x tile

    if (tid < CHUNK) {
        int t = t0 + tid;
        float dt = 0.0f;
        if (t > 0)
            dt = fmaxf(delta[b * TT + t] - delta[b * TT + t - 1], 0.0f);
#pragma unroll
        for (int m = 0; m < MM; m++) {
            float a = expf(-dt / tau[m]);
            s_al[tid * MM + m] = make_float2(a, 1.0f - a);
        }
    }

    // cooperative coalesced load of the x chunk (8 independent LDG.128/thread)
    {
        const float4* xp = (const float4*)x + ((size_t)b * TT + t0) * D4;
#pragma unroll
        for (int i = 0; i < (CHUNK * D4) / 256; i++)
            s_x[i * 256 + tid] = __ldg(xp + i * 256 + tid);
    }
    __syncthreads();

    if (tid < MM) {
        float p = 1.0f;
#pragma unroll
        for (int t = 0; t < CHUNK; t++) p *= s_al[t * MM + tid].x;
        g_A[(b * NC + c) * MM + tid] = p;
    }

    float4 s0 = make_float4(0.f, 0.f, 0.f, 0.f);
    float4 s1 = make_float4(0.f, 0.f, 0.f, 0.f);

#pragma unroll 8
    for (int t = 0; t < CHUNK; t++) {
        float4 xv = s_x[t * D4 + d4];
        float2 a0 = s_al[t * MM + m0];
        float2 a1 = s_al[t * MM + m1];
        s0.x = fmaf(a0.x, s0.x, a0.y * xv.x);
        s0.y = fmaf(a0.x, s0.y, a0.y * xv.y);
        s0.z = fmaf(a0.x, s0.z, a0.y * xv.z);
        s0.w = fmaf(a0.x, s0.w, a0.y * xv.w);
        s1.x = fmaf(a1.x, s1.x, a1.y * xv.x);
        s1.y = fmaf(a1.x, s1.y, a1.y * xv.y);
        s1.z = fmaf(a1.x, s1.z, a1.y * xv.z);
        s1.w = fmaf(a1.x, s1.w, a1.y * xv.w);
    }

    float4* Lp = (float4*)g_L + (size_t)(b * NC + c) * RPB + d4;
    Lp[m0 * D4] = s0;
    Lp[m1 * D4] = s1;
}

// ---------------------------------------------------------------------------
// Kernel 2: sequential exclusive scan across chunks per (b, m, d4).
// [R4 verbatim — implied ~5 us]
// ---------------------------------------------------------------------------
__global__ __launch_bounds__(64) void k_scan()
{
    int idx = blockIdx.x * 64 + threadIdx.x;    // 0 .. B*M*D4-1 = 4095
    int b = idx >> 9;          // / RPB
    int r = idx & (RPB - 1);
    int m = r >> 6;            // / D4

    const float4* Lp = (const float4*)g_L;
    float4* Sp = (float4*)g_S;

    float4 s = make_float4(0.f, 0.f, 0.f, 0.f);
#pragma unroll 8
    for (int c = 0; c < NC; c++) {
        size_t off = (size_t)(b * NC + c) * RPB + r;
        float4 L = __ldg(Lp + off);
        float  A = __ldg(&g_A[(b * NC + c) * MM + m]);
        Sp[off] = s;
        s.x = fmaf(A, s.x, L.x);
        s.y = fmaf(A, s.y, L.y);
        s.z = fmaf(A, s.z, L.z);
        s.w = fmaf(A, s.w, L.w);
    }
}

// ---------------------------------------------------------------------------
// Kernel 3 [THE ONE CHANGE vs R4]: replay, thin threads.
// Block = (b, c). 512 threads: tid = m*64 + d4, ONE float4 state per thread.
// ~32 regs -> 4 blocks/SM (2048 thr, 100% occ) = max independent store streams.
// x staged once in 32 KB smem (8-way broadcast LDS); __stcs streaming stores.
// ---------------------------------------------------------------------------
__global__ __launch_bounds__(512) void k_final(
    const float* __restrict__ x, const float* __restrict__ delta,
    const float* __restrict__ tau, float* __restrict__ out)
{
    int blk = blockIdx.x;
    int b = blk >> 7;
    int c = blk & (NC - 1);
    int t0 = c * CHUNK;
    int tid = threadIdx.x;     // = m*64 + d4 = r
    int d4 = tid & 63;
    int m  = tid >> 6;

    __shared__ float2 s_al[CHUNK * MM];
    __shared__ float4 s_x[CHUNK * D4];      // 32 KB x tile

    if (tid < 32) {
        int t = t0 + tid;
        float dt = 0.0f;
        if (t > 0)
            dt = fmaxf(delta[b * TT + t] - delta[b * TT + t - 1], 0.0f);
#pragma unroll
        for (int mm = 0; mm < MM; mm++) {
            float a = expf(-dt / tau[mm]);
            s_al[tid * MM + mm] = make_float2(a, 1.0f - a);
        }
    }

    // cooperative coalesced x tile fill (4 independent LDG.128 per thread)
    {
        const float4* xp = (const float4*)x + ((size_t)b * TT + t0) * D4;
#pragma unroll
        for (int i = 0; i < (CHUNK * D4) / 512; i++)
            s_x[i * 512 + tid] = __ldg(xp + i * 512 + tid);
    }

    // chunk-initial state: r == tid, coalesced LDG.128
    float4 s = ((const float4*)g_S)[(size_t)(b * NC + c) * RPB + tid];

    __syncthreads();

    float4* op = (float4*)out + ((size_t)(b * TT + t0)) * RPB + tid;

#pragma unroll 8
    for (int t = 0; t < CHUNK; t++) {
        float4 xv = s_x[t * D4 + d4];          // 8-way broadcast across m
        float2 al = s_al[t * MM + m];
        s.x = fmaf(al.x, s.x, al.y * xv.x);
        s.y = fmaf(al.x, s.y, al.y * xv.y);
        s.z = fmaf(al.x, s.z, al.y * xv.z);
        s.w = fmaf(al.x, s.w, al.y * xv.w);
        __stcs(op + (size_t)t * RPB, s);       // contiguous 8 KB row per t
    }
}

extern "C" void kernel_launch(void* const* d_in, const int* in_sizes, int n_in,
                              void* d_out, int out_size)
{
    const float* x     = (const float*)d_in[0];
    const float* delta = (const float*)d_in[1];
    const float* tau   = (const float*)d_in[2];
    float* out = (float*)d_out;

    k_locals<<<BB * NC, 256>>>(x, delta, tau);
    k_scan<<<64, 64>>>();
    k_final<<<BB * NC, 512>>>(x, delta, tau, out);
}

// round 17
// speedup vs baseline: 1.8224x; 1.0049x over previous
#include <cuda_runtime.h>
#include <cuda_bf16.h>
#include <math.h>

// Problem constants
#define BB   8
#define TT   4096
#define DD   256
#define MM   8
#define CHUNK 32
#define SUB  8                 // subchunk length inside k_locals
#define NC   (TT / CHUNK)      // 128 chunks along T
#define D4   (DD / 4)          // 64 float4 groups per row
#define RPB  (MM * D4)         // 512 float4 "r" slots per (b,c)

// Scratch (static device allocations — no runtime alloc)
__device__ float g_L[(size_t)BB * NC * MM * DD];   // chunk-local final states, 8 MB
__device__ float g_S[(size_t)BB * NC * MM * DD];   // chunk initial states,     8 MB
__device__ float g_A[BB * NC * MM];                // chunk decay products

// ---------------------------------------------------------------------------
// Kernel 1 [THE ONE CHANGE vs R16]: per-chunk local recurrence -> chunk L, A.
// Block = (b, c). 256 threads: tid = g*64 + d4.
// Phase A: group g runs the 8-step local recurrence of subchunk g for ALL 8 m,
//          reading x straight to registers (1x coalesced LDG, no smem x tile).
// Phase B: fold the 4 subchunk (L,A) into chunk-level L via smem (cheap:
//          8 LDS.128/thread instead of 32 on the old x-tile path).
// ---------------------------------------------------------------------------
__global__ __launch_bounds__(256) void k_locals(
    const float* __restrict__ x, const float* __restrict__ delta,
    const float* __restrict__ tau)
{
    int blk = blockIdx.x;
    int b = blk >> 7;          // / NC
    int c = blk & (NC - 1);
    int t0 = c * CHUNK;
    int tid = threadIdx.x;
    int d4 = tid & 63;
    int g  = tid >> 6;         // subchunk 0..3

    __shared__ float2 s_al[CHUNK * MM];        // (a, 1-a) per (t, m)
    __shared__ float  s_Ag[4 * MM];            // subchunk decay products
    __shared__ float4 s_Lg[4 * MM * 64];       // subchunk local finals, 32 KB

    // warp 0: alphas for all 32 t, then subchunk products (lane = gg*8 + mm)
    if (tid < 32) {
        int t = t0 + tid;
        float dt = 0.0f;
        if (t > 0)
            dt = fmaxf(delta[b * TT + t] - delta[b * TT + t - 1], 0.0f);
#pragma unroll
        for (int m = 0; m < MM; m++) {
            float a = expf(-dt / tau[m]);
            s_al[tid * MM + m] = make_float2(a, 1.0f - a);
        }
        __syncwarp();
        int gg = tid >> 3, mm = tid & 7;
        float p = 1.0f;
#pragma unroll
        for (int t2 = 0; t2 < SUB; t2++) p *= s_al[(gg * SUB + t2) * MM + mm].x;
        s_Ag[gg * MM + mm] = p;
    }

    // prefetch the 8 x rows of this thread's subchunk (independent LDG.128)
    const float4* xp = (const float4*)x + ((size_t)b * TT + t0 + g * SUB) * D4 + d4;
    float4 xv[SUB];
#pragma unroll
    for (int t = 0; t < SUB; t++) xv[t] = __ldg(xp + t * D4);

    __syncthreads();   // alphas ready

    // local recurrence for all 8 m over this subchunk
    float4 s[MM];
#pragma unroll
    for (int m = 0; m < MM; m++) s[m] = make_float4(0.f, 0.f, 0.f, 0.f);

#pragma unroll
    for (int t = 0; t < SUB; t++) {
#pragma unroll
        for (int m = 0; m < MM; m++) {
            float2 al = s_al[(g * SUB + t) * MM + m];
            s[m].x = fmaf(al.x, s[m].x, al.y * xv[t].x);
            s[m].y = fmaf(al.x, s[m].y, al.y * xv[t].y);
            s[m].z = fmaf(al.x, s[m].z, al.y * xv[t].z);
            s[m].w = fmaf(al.x, s[m].w, al.y * xv[t].w);
        }
    }

#pragma unroll
    for (int m = 0; m < MM; m++) s_Lg[(g * MM + m) * 64 + d4] = s[m];
    __syncthreads();

    // fold subchunks: thread (g, d4) produces chunk L for m-pair {2g, 2g+1}
    int m0 = g * 2, m1 = m0 + 1;
    float4 a0 = make_float4(0.f, 0.f, 0.f, 0.f);
    float4 a1 = make_float4(0.f, 0.f, 0.f, 0.f);
#pragma unroll
    for (int gg = 0; gg < 4; gg++) {
        float A0 = s_Ag[gg * MM + m0];
        float A1 = s_Ag[gg * MM + m1];
        float4 L0 = s_Lg[(gg * MM + m0) * 64 + d4];
        float4 L1 = s_Lg[(gg * MM + m1) * 64 + d4];
        a0.x = fmaf(A0, a0.x, L0.x);  a0.y = fmaf(A0, a0.y, L0.y);
        a0.z = fmaf(A0, a0.z, L0.z);  a0.w = fmaf(A0, a0.w, L0.w);
        a1.x = fmaf(A1, a1.x, L1.x);  a1.y = fmaf(A1, a1.y, L1.y);
        a1.z = fmaf(A1, a1.z, L1.z);  a1.w = fmaf(A1, a1.w, L1.w);
    }

    float4* Lp = (float4*)g_L + (size_t)(b * NC + c) * RPB + d4;
    Lp[m0 * D4] = a0;
    Lp[m1 * D4] = a1;

    if (tid < MM) {
        float p = 1.0f;
#pragma unroll
        for (int gg = 0; gg < 4; gg++) p *= s_Ag[gg * MM + tid];
        g_A[(b * NC + c) * MM + tid] = p;
    }
}

// ---------------------------------------------------------------------------
// Kernel 2: sequential exclusive scan across chunks per (b, m, d4).
// [R4/R16 verbatim — implied ~5 us]
// ---------------------------------------------------------------------------
__global__ __launch_bounds__(64) void k_scan()
{
    int idx = blockIdx.x * 64 + threadIdx.x;    // 0 .. B*M*D4-1 = 4095
    int b = idx >> 9;          // / RPB
    int r = idx & (RPB - 1);
    int m = r >> 6;            // / D4

    const float4* Lp = (const float4*)g_L;
    float4* Sp = (float4*)g_S;

    float4 s = make_float4(0.f, 0.f, 0.f, 0.f);
#pragma unroll 8
    for (int c = 0; c < NC; c++) {
        size_t off = (size_t)(b * NC + c) * RPB + r;
        float4 L = __ldg(Lp + off);
        float  A = __ldg(&g_A[(b * NC + c) * MM + m]);
        Sp[off] = s;
        s.x = fmaf(A, s.x, L.x);
        s.y = fmaf(A, s.y, L.y);
        s.z = fmaf(A, s.z, L.z);
        s.w = fmaf(A, s.w, L.w);
    }
}

// ---------------------------------------------------------------------------
// Kernel 3: replay, thin threads. [R16 verbatim — measured neutral vs R4,
// k_final is near the memory wall at ~5.4 TB/s aggregate]
// ---------------------------------------------------------------------------
__global__ __launch_bounds__(512) void k_final(
    const float* __restrict__ x, const float* __restrict__ delta,
    const float* __restrict__ tau, float* __restrict__ out)
{
    int blk = blockIdx.x;
    int b = blk >> 7;
    int c = blk & (NC - 1);
    int t0 = c * CHUNK;
    int tid = threadIdx.x;     // = m*64 + d4 = r
    int d4 = tid & 63;
    int m  = tid >> 6;

    __shared__ float2 s_al[CHUNK * MM];
    __shared__ float4 s_x[CHUNK * D4];      // 32 KB x tile

    if (tid < 32) {
        int t = t0 + tid;
        float dt = 0.0f;
        if (t > 0)
            dt = fmaxf(delta[b * TT + t] - delta[b * TT + t - 1], 0.0f);
#pragma unroll
        for (int mm = 0; mm < MM; mm++) {
            float a = expf(-dt / tau[mm]);
            s_al[tid * MM + mm] = make_float2(a, 1.0f - a);
        }
    }

    // cooperative coalesced x tile fill (4 independent LDG.128 per thread)
    {
        const float4* xp = (const float4*)x + ((size_t)b * TT + t0) * D4;
#pragma unroll
        for (int i = 0; i < (CHUNK * D4) / 512; i++)
            s_x[i * 512 + tid] = __ldg(xp + i * 512 + tid);
    }

    // chunk-initial state: r == tid, coalesced LDG.128
    float4 s = ((const float4*)g_S)[(size_t)(b * NC + c) * RPB + tid];

    __syncthreads();

    float4* op = (float4*)out + ((size_t)(b * TT + t0)) * RPB + tid;

#pragma unroll 8
    for (int t = 0; t < CHUNK; t++) {
        float4 xv = s_x[t * D4 + d4];          // 8-way broadcast across m
        float2 al = s_al[t * MM + m];
        s.x = fmaf(al.x, s.x, al.y * xv.x);
        s.y = fmaf(al.x, s.y, al.y * xv.y);
        s.z = fmaf(al.x, s.z, al.y * xv.z);
        s.w = fmaf(al.x, s.w, al.y * xv.w);
        __stcs(op + (size_t)t * RPB, s);       // contiguous 8 KB row per t
    }
}

extern "C" void kernel_launch(void* const* d_in, const int* in_sizes, int n_in,
                              void* d_out, int out_size)
{
    const float* x     = (const float*)d_in[0];
    const float* delta = (const float*)d_in[1];
    const float* tau   = (const float*)d_in[2];
    float* out = (float*)d_out;

    k_locals<<<BB * NC, 256>>>(x, delta, tau);
    k_scan<<<64, 64>>>();
    k_final<<<BB * NC, 512>>>(x, delta, tau, out);
}